// round 2
// baseline (speedup 1.0000x reference)
#include <cuda_runtime.h>

#define NVOX (64*64*64)        // 262144 voxels
#define BKN 28                 // 4 batches * 7 moving parts
#define CHUNKS 32              // partial-reduction chunks per (b,k)
#define RED_THREADS 256
#define APPLY_THREADS 256

// Scratch (no allocations allowed): deterministic partials
__device__ float g_partial[BKN * CHUNKS * 4];

// ---------------------------------------------------------------------------
// Pass 1: per-(b,k) weighted sums (sum m, sum m*gx, sum m*gy, sum m*gz).
// Each block owns exactly 2048 float4 = 8 per thread; all 8 loads are issued
// up-front (MLP=8) before any accumulation to hide DRAM/L2 latency.
// grids is a separable meshgrid: we touch only 3*64 axis values.
// ---------------------------------------------------------------------------
__global__ void __launch_bounds__(RED_THREADS)
reduce_k(const float* __restrict__ mask, const float* __restrict__ grids)
{
    const int bk    = blockIdx.x >> 5;     // / CHUNKS
    const int chunk = blockIdx.x & 31;     // % CHUNKS
    const int b = bk / 7, k = bk % 7;
    const int tid = threadIdx.x;

    __shared__ float ax[64], ay[64], az[64];
    if (tid < 64) {
        ax[tid] = grids[tid << 12];                 // gx[i,0,0]
        ay[tid] = grids[NVOX + (tid << 6)];         // gy[0,j,0]
        az[tid] = grids[2 * NVOX + tid];            // gz[0,0,k]
    }

    const int chunk_f4 = NVOX / CHUNKS / 4;         // 2048 float4 per block
    const float4* m4 = (const float4*)(mask + ((size_t)(b * 8 + k)) * NVOX)
                       + (size_t)chunk * chunk_f4;
    const int vbase = chunk * (NVOX / CHUNKS);

    // ---- issue ALL 8 loads before consuming any (explicit MLP=8) ----
    float4 mv[8];
#pragma unroll
    for (int t = 0; t < 8; ++t)
        mv[t] = m4[t * RED_THREADS + tid];

    __syncthreads();   // axes ready (placed after loads; loads don't need smem)

    float s0 = 0.f, sx = 0.f, sy = 0.f, sz = 0.f;
#pragma unroll
    for (int t = 0; t < 8; ++t) {
        const int idx4 = t * RED_THREADS + tid;
        const int v  = vbase + (idx4 << 2);
        const int i  = v >> 12;
        const int j  = (v >> 6) & 63;
        const int kk = v & 63;                      // multiple of 4
        const float ms = (mv[t].x + mv[t].y) + (mv[t].z + mv[t].w);
        s0 += ms;
        sx = fmaf(ax[i], ms, sx);
        sy = fmaf(ay[j], ms, sy);
        sz = fmaf(az[kk],     mv[t].x,
             fmaf(az[kk + 1], mv[t].y,
             fmaf(az[kk + 2], mv[t].z,
             fmaf(az[kk + 3], mv[t].w, sz))));
    }

    // warp tree reduce (deterministic)
#pragma unroll
    for (int off = 16; off; off >>= 1) {
        s0 += __shfl_down_sync(0xFFFFFFFFu, s0, off);
        sx += __shfl_down_sync(0xFFFFFFFFu, sx, off);
        sy += __shfl_down_sync(0xFFFFFFFFu, sy, off);
        sz += __shfl_down_sync(0xFFFFFFFFu, sz, off);
    }
    __shared__ float red[8][4];
    const int w = tid >> 5, l = tid & 31;
    if (l == 0) { red[w][0] = s0; red[w][1] = sx; red[w][2] = sy; red[w][3] = sz; }
    __syncthreads();
    if (tid == 0) {
        float r0 = 0.f, r1 = 0.f, r2 = 0.f, r3 = 0.f;
#pragma unroll
        for (int i = 0; i < 8; ++i) {
            r0 += red[i][0]; r1 += red[i][1]; r2 += red[i][2]; r3 += red[i][3];
        }
        float* p = g_partial + (bk * CHUNKS + chunk) * 4;
        p[0] = r0; p[1] = r1; p[2] = r2; p[3] = r3;
    }
}

// ---------------------------------------------------------------------------
// Pass 2 (fused coef + apply):
// Threads 0..6 of every block fold this batch's partials into coefficients
//   M = R - I  (row-major 9),  d = p + t - R p  (3)
// then all threads compute motion[b,c,v] = sum_k mask[b,k,v]*(M_bk[c,:].g_v + d_bk[c])
// k=7 contributes exactly zero and is skipped.
// ---------------------------------------------------------------------------
__global__ void __launch_bounds__(APPLY_THREADS)
apply_k(const float* __restrict__ mask, const float* __restrict__ grids,
        const float* __restrict__ trans_vec, const float* __restrict__ rot_mat,
        float* __restrict__ out)
{
    const int blocksPerB = NVOX / 4 / APPLY_THREADS;   // 256
    const int b   = blockIdx.x / blocksPerB;
    const int blk = blockIdx.x % blocksPerB;
    const int tid = threadIdx.x;

    __shared__ float cf[84];            // 7 * 12 coefficients for this batch
    __shared__ float ax[64], ay[64], az[64];
    if (tid < 64) {
        ax[tid] = grids[tid << 12];
        ay[tid] = grids[NVOX + (tid << 6)];
        az[tid] = grids[2 * NVOX + tid];
    }
    if (tid < 7) {
        const int bk = b * 7 + tid;
        const float* p = g_partial + bk * CHUNKS * 4;
        float s0 = 0.f, sx = 0.f, sy = 0.f, sz = 0.f;
#pragma unroll
        for (int c = 0; c < CHUNKS; ++c) {
            s0 += p[c * 4 + 0]; sx += p[c * 4 + 1];
            sy += p[c * 4 + 2]; sz += p[c * 4 + 3];
        }
        const float inv = 1.f / s0;
        const float pv[3] = { sx * inv, sy * inv, sz * inv };
        const float* R = rot_mat  + bk * 9;
        const float* t = trans_vec + bk * 3;
        float* c = cf + tid * 12;
#pragma unroll
        for (int r = 0; r < 3; ++r) {
            const float Rp = R[r * 3 + 0] * pv[0] + R[r * 3 + 1] * pv[1] + R[r * 3 + 2] * pv[2];
            c[r * 3 + 0] = R[r * 3 + 0] - (r == 0 ? 1.f : 0.f);
            c[r * 3 + 1] = R[r * 3 + 1] - (r == 1 ? 1.f : 0.f);
            c[r * 3 + 2] = R[r * 3 + 2] - (r == 2 ? 1.f : 0.f);
            c[9 + r]     = pv[r] + t[r] - Rp;
        }
    }

    const int idx4 = blk * APPLY_THREADS + tid;
    const float4* mb = (const float4*)mask + ((size_t)b * 8) * (NVOX / 4) + idx4;

    // ---- issue all 7 mask loads before consuming (MLP=7) ----
    float4 mv[7];
#pragma unroll
    for (int k = 0; k < 7; ++k)
        mv[k] = mb[(size_t)k * (NVOX / 4)];

    __syncthreads();   // cf + axes ready

    const int v  = idx4 << 2;
    const int i  = v >> 12;
    const int j  = (v >> 6) & 63;
    const int kk = v & 63;
    const float gx = ax[i], gy = ay[j];
    const float gz[4] = { az[kk], az[kk + 1], az[kk + 2], az[kk + 3] };

    float mot[3][4] = {};
#pragma unroll
    for (int k = 0; k < 7; ++k) {
        const float mvv[4] = { mv[k].x, mv[k].y, mv[k].z, mv[k].w };
        const float* c = cf + k * 12;
#pragma unroll
        for (int cc = 0; cc < 3; ++cc) {
            const float m0 = c[cc * 3 + 0], m1 = c[cc * 3 + 1], m2 = c[cc * 3 + 2];
            const float base = fmaf(m0, gx, fmaf(m1, gy, c[9 + cc]));
#pragma unroll
            for (int t = 0; t < 4; ++t)
                mot[cc][t] = fmaf(mvv[t], fmaf(m2, gz[t], base), mot[cc][t]);
        }
    }

    float4* o4 = (float4*)out;
#pragma unroll
    for (int cc = 0; cc < 3; ++cc) {
        float4 o = { mot[cc][0], mot[cc][1], mot[cc][2], mot[cc][3] };
        o4[((size_t)b * 3 + cc) * (NVOX / 4) + idx4] = o;
    }
}

// ---------------------------------------------------------------------------
extern "C" void kernel_launch(void* const* d_in, const int* in_sizes, int n_in,
                              void* d_out, int out_size)
{
    const float* mask = nullptr;
    const float* tv   = nullptr;
    const float* rm   = nullptr;
    const float* gr   = nullptr;
    for (int i = 0; i < n_in; ++i) {
        switch (in_sizes[i]) {
            case 8388608: mask = (const float*)d_in[i]; break;   // (4,8,64,64,64)
            case 84:      tv   = (const float*)d_in[i]; break;   // (4,7,3)
            case 252:     rm   = (const float*)d_in[i]; break;   // (4,7,3,3)
            case 786432:  gr   = (const float*)d_in[i]; break;   // (3,64,64,64)
        }
    }
    reduce_k<<<BKN * CHUNKS, RED_THREADS>>>(mask, gr);
    apply_k<<<4 * (NVOX / 4 / APPLY_THREADS), APPLY_THREADS>>>(mask, gr, tv, rm, (float*)d_out);
}